// round 14
// baseline (speedup 1.0000x reference)
#include <cuda_runtime.h>
#include <cuda_bf16.h>
#include <cfloat>
#include <cstddef>

// Problem constants
#define BB 8
#define WW 64
#define NN 128
#define DD 1024
#define PP 512
#define VV 256
#define NBW (BB*WW)          // 512 windows
#define OUTD (DD+VV)         // 1280
#define NKB (DD+NN)          // 1152 combined W_k rows + pos rows
#define PREP_BLOCKS ((NKB*PP+255)/256)   // 2304

// Scratch (device globals; no allocation allowed)
__device__ float g_S4 [4*NBW*DD];    // masked partial sums (4 quarter slabs)
__device__ float g_LEN[NBW];         // valid lengths
__device__ float g_WE [NBW*PP];      // reduced WE
__device__ float g_Q  [NBW*PP];      // reduced Q
__device__ float g_KB [NKB*PP];      // [W_k(1024 rows); POS(128 rows)]
__device__ float g_Y  [NBW*DD];      // attn-weighted x sum
__device__ float g_P1 [4*NBW*NKB];   // partials: F1(8x512x512) / F3(4x512x1152)
__device__ float g_P2 [16*NBW*VV];   // partials: F2(8x512x512) / F4(16x512x256)

// ---------------------------------------------------------------------------
// prep: W_k rows + sinusoidal pos rows into g_KB; last 2 blocks compute lengths
// ---------------------------------------------------------------------------
__global__ void prep_kernel(const float* __restrict__ Wk,
                            const int* __restrict__ mask) {
    if (blockIdx.x >= PREP_BLOCKS) {
        // lengths: one thread per window
        int w = (blockIdx.x - PREP_BLOCKS) * 256 + threadIdx.x;
        if (w < NBW) {
            const int4* m4 = (const int4*)(mask + (size_t)w * NN);
            int c = 0;
            #pragma unroll 8
            for (int i = 0; i < 32; i++) {
                int4 v = m4[i];
                c += (v.x == 0) + (v.y == 0) + (v.z == 0) + (v.w == 0);
            }
            g_LEN[w] = fmaxf((float)c, 1.0f);
        }
        return;
    }
    int idx = blockIdx.x * blockDim.x + threadIdx.x;
    if (idx >= NKB * PP) return;
    int row = idx >> 9;      // 0..1151
    int i   = idx & 511;
    if (row < DD) {
        g_KB[idx] = Wk[idx];
    } else {
        int j = row - DD;    // pos row 0..127
        const float LOG1E4 = 9.210340371976184f;
        float val;
        if (i < 256) {
            float invf = expf(-((float)i / 256.0f) * LOG1E4);
            val = sinf((float)j * invf);
        } else {
            float invf = expf(-((float)(i - 256) / 256.0f) * LOG1E4);
            val = cosf((float)j * invf);
        }
        g_KB[idx] = val;
    }
}

// ---------------------------------------------------------------------------
// Kernel 1: copy x -> out[..., :1024] + masked partial sum.
// 2048 blocks: block handles quarter q (32 rows) of window bw.
// Streaming loads (x never needed in L2 until k3, much later) and stores.
// Partial sums land in slab q of g_S4; F1 sums the 4 slabs (ASUM=4).
// ---------------------------------------------------------------------------
__global__ void __launch_bounds__(256) k1_sum_copy(
    const float* __restrict__ x, const int* __restrict__ mask,
    float* __restrict__ out)
{
    int b  = blockIdx.x;
    int bw = b >> 2;
    int q  = b & 3;
    int t  = threadIdx.x;
    __shared__ int smask[32];
    if (t < 32) smask[t] = mask[bw * NN + q * 32 + t];
    __syncthreads();

    const float4* x4 = (const float4*)(x + ((size_t)bw * NN + q * 32) * DD);
    float4* o4 = (float4*)(out + ((size_t)bw * NN + q * 32) * OUTD);
    float4 acc = make_float4(0.f, 0.f, 0.f, 0.f);
    #pragma unroll 4
    for (int j = 0; j < 32; j++) {
        float4 v = __ldcs(&x4[j * 256 + t]);
        __stcs(&o4[(size_t)j * 320 + t], v);
        if (smask[j] == 0) {
            acc.x += v.x; acc.y += v.y; acc.z += v.z; acc.w += v.w;
        }
    }
    ((float4*)g_S4)[((size_t)q * NBW + bw) * 256 + t] = acc;
}

// ---------------------------------------------------------------------------
// Split-K GEMM (proven 32x64 config). ASUM: A := sum of ASUM slabs
// (slab stride NBW*lda). grid = (N/64, 16, SPLIT). 128 thr, 4x4 microtile,
// BK=16, double-buffered smem, register prefetch, one sync per stage.
// TB=0: B is [K,N] (ldb=N); TB=1: B is [N,K] (ldb=K).
// Output: partial slab part[bz][512][N].
// ---------------------------------------------------------------------------
template<bool TB, int ASUM>
__global__ void __launch_bounds__(128) gemm_sk(
    const float* __restrict__ A, const float* __restrict__ B,
    float* __restrict__ part, int N, int lda, int ldb, int Kchunk)
{
    __shared__ float As[2][16][33];
    __shared__ float Bs[2][16][68];
    const int tid = threadIdx.x;
    const int row0  = blockIdx.y * 32;
    const int col0  = blockIdx.x * 64;
    const int kbase = blockIdx.z * Kchunk;

    const int ty = tid >> 4, tx = tid & 15;
    const int arow = tid >> 2;
    const int akc  = (tid & 3) << 2;
    const size_t AS = (size_t)NBW * lda;
    const float* Ag = A + (size_t)(row0 + arow) * lda + kbase + akc;

    const int bk  = tid >> 3;
    const int bn  = (tid & 7) << 3;
    const int tn  = tid & 63;
    const int tkh = (tid >> 6) << 3;

    float acc[4][4] = {};
    float4 va[ASUM];
    float4 rb0, rb1;

    #pragma unroll
    for (int z = 0; z < ASUM; z++) va[z] = *(const float4*)(Ag + (size_t)z * AS);
    if (!TB) {
        const float* bp = B + (size_t)(kbase + bk) * ldb + col0 + bn;
        rb0 = *(const float4*)bp; rb1 = *(const float4*)(bp + 4);
    } else {
        const float* bp = B + (size_t)(col0 + tn) * ldb + kbase + tkh;
        rb0 = *(const float4*)bp; rb1 = *(const float4*)(bp + 4);
    }
    {
        float4 s = va[0];
        #pragma unroll
        for (int z = 1; z < ASUM; z++) { s.x += va[z].x; s.y += va[z].y; s.z += va[z].z; s.w += va[z].w; }
        As[0][akc+0][arow] = s.x; As[0][akc+1][arow] = s.y;
        As[0][akc+2][arow] = s.z; As[0][akc+3][arow] = s.w;
    }
    if (!TB) {
        *(float4*)&Bs[0][bk][bn]     = rb0;
        *(float4*)&Bs[0][bk][bn + 4] = rb1;
    } else {
        Bs[0][tkh+0][tn] = rb0.x; Bs[0][tkh+1][tn] = rb0.y;
        Bs[0][tkh+2][tn] = rb0.z; Bs[0][tkh+3][tn] = rb0.w;
        Bs[0][tkh+4][tn] = rb1.x; Bs[0][tkh+5][tn] = rb1.y;
        Bs[0][tkh+6][tn] = rb1.z; Bs[0][tkh+7][tn] = rb1.w;
    }
    __syncthreads();

    const int nst = Kchunk >> 4;
    for (int s = 0; s < nst; s++) {
        const int cur = s & 1;
        if (s + 1 < nst) {
            const int k0 = (s + 1) << 4;
            #pragma unroll
            for (int z = 0; z < ASUM; z++)
                va[z] = *(const float4*)(Ag + k0 + (size_t)z * AS);
            if (!TB) {
                const float* bp = B + (size_t)(kbase + k0 + bk) * ldb + col0 + bn;
                rb0 = *(const float4*)bp; rb1 = *(const float4*)(bp + 4);
            } else {
                const float* bp = B + (size_t)(col0 + tn) * ldb + kbase + k0 + tkh;
                rb0 = *(const float4*)bp; rb1 = *(const float4*)(bp + 4);
            }
        }
        #pragma unroll
        for (int kk = 0; kk < 16; kk++) {
            float a[4], b[4];
            #pragma unroll
            for (int i = 0; i < 4; i++) a[i] = As[cur][kk][ty + 8 * i];
            #pragma unroll
            for (int j = 0; j < 4; j++) b[j] = Bs[cur][kk][tx + 16 * j];
            #pragma unroll
            for (int i = 0; i < 4; i++)
                #pragma unroll
                for (int j = 0; j < 4; j++)
                    acc[i][j] = fmaf(a[i], b[j], acc[i][j]);
        }
        if (s + 1 < nst) {
            const int nxt = cur ^ 1;
            {
                float4 sv = va[0];
                #pragma unroll
                for (int z = 1; z < ASUM; z++) { sv.x += va[z].x; sv.y += va[z].y; sv.z += va[z].z; sv.w += va[z].w; }
                As[nxt][akc+0][arow] = sv.x; As[nxt][akc+1][arow] = sv.y;
                As[nxt][akc+2][arow] = sv.z; As[nxt][akc+3][arow] = sv.w;
            }
            if (!TB) {
                *(float4*)&Bs[nxt][bk][bn]     = rb0;
                *(float4*)&Bs[nxt][bk][bn + 4] = rb1;
            } else {
                Bs[nxt][tkh+0][tn] = rb0.x; Bs[nxt][tkh+1][tn] = rb0.y;
                Bs[nxt][tkh+2][tn] = rb0.z; Bs[nxt][tkh+3][tn] = rb0.w;
                Bs[nxt][tkh+4][tn] = rb1.x; Bs[nxt][tkh+5][tn] = rb1.y;
                Bs[nxt][tkh+6][tn] = rb1.z; Bs[nxt][tkh+7][tn] = rb1.w;
            }
            __syncthreads();
        }
    }

    float* Cp = part + (size_t)blockIdx.z * NBW * N;
    #pragma unroll
    for (int i = 0; i < 4; i++) {
        const int m = row0 + ty + 8 * i;
        #pragma unroll
        for (int j = 0; j < 4; j++)
            Cp[(size_t)m * N + col0 + tx + 16 * j] = acc[i][j];
    }
}

// ---------------------------------------------------------------------------
// reduce_k: C = sum of SPLIT partial slabs; EPI==1: relu(sum / lenv[row]).
// ---------------------------------------------------------------------------
template<int EPI, int SPLIT>
__global__ void __launch_bounds__(256) reduce_k(
    const float* __restrict__ part, float* __restrict__ C,
    int MN, int N, const float* __restrict__ lenv)
{
    int idx4 = blockIdx.x * blockDim.x + threadIdx.x;
    if (idx4 * 4 >= MN) return;
    const float4* p4 = (const float4*)part;
    float4 s = p4[idx4];
    #pragma unroll
    for (int z = 1; z < SPLIT; z++) {
        float4 v = p4[(size_t)z * (MN / 4) + idx4];
        s.x += v.x; s.y += v.y; s.z += v.z; s.w += v.w;
    }
    if (EPI == 1) {
        int row = (idx4 * 4) / N;
        float inv = 1.0f / lenv[row];
        s.x = fmaxf(s.x * inv, 0.f); s.y = fmaxf(s.y * inv, 0.f);
        s.z = fmaxf(s.z * inv, 0.f); s.w = fmaxf(s.w * inv, 0.f);
    }
    ((float4*)C)[idx4] = s;
}

// ---------------------------------------------------------------------------
// Kernel 3: per-window attention, 512 threads.
// Sums the 4 RPB partial slabs; 16 warps for the dots pass; weighted-sum
// pass split across two 64-row halves per column.
// ---------------------------------------------------------------------------
__global__ void __launch_bounds__(512) k3_attn(
    const float* __restrict__ x, const int* __restrict__ mask,
    const float* __restrict__ ps_ptr)
{
    int bw = blockIdx.x;
    int t = threadIdx.x;
    int warp = t >> 5, lane = t & 31;
    __shared__ float sr[DD];
    __shared__ float spb[NN];
    __shared__ float sdots[NN];
    __shared__ float red[NN];
    __shared__ float s_m, s_sum;
    __shared__ float4 sh[256];

    const float* rp = g_P1 + (size_t)bw * NKB;
    const size_t SL = (size_t)NBW * NKB;
    if (t < 256) {
        float4 a = ((const float4*)rp)[t];
        #pragma unroll
        for (int z = 1; z < 4; z++) {
            float4 b = ((const float4*)(rp + z * SL))[t];
            a.x += b.x; a.y += b.y; a.z += b.z; a.w += b.w;
        }
        ((float4*)sr)[t] = a;
    } else if (t < 256 + NN) {
        int i = t - 256;
        float v = rp[DD + i];
        #pragma unroll
        for (int z = 1; z < 4; z++) v += rp[z * SL + DD + i];
        spb[i] = v;
    }
    __syncthreads();

    const float* xw = x + (size_t)bw * NN * DD;
    float ps = ps_ptr[0];
    const float rs = 0.044194173824159216f;   // 512^-0.5

    // dots: 16 warps, 8 rows each
    for (int j = warp; j < NN; j += 16) {
        const float4* row = (const float4*)(xw + (size_t)j * DD);
        const float4* r4  = (const float4*)sr;
        float s = 0.f;
        #pragma unroll
        for (int it = 0; it < 8; it++) {
            float4 v = row[lane + it * 32];
            float4 r = r4 [lane + it * 32];
            s += v.x*r.x + v.y*r.y + v.z*r.z + v.w*r.w;
        }
        #pragma unroll
        for (int o = 16; o > 0; o >>= 1) s += __shfl_xor_sync(0xffffffffu, s, o);
        if (lane == 0) {
            sdots[j] = (mask[bw * NN + j] != 0) ? -FLT_MAX
                                                : (s + ps * spb[j]) * rs;
        }
    }
    __syncthreads();

    // softmax over 128 values
    if (t < NN) red[t] = sdots[t];
    __syncthreads();
    for (int s = 64; s > 0; s >>= 1) {
        if (t < s) red[t] = fmaxf(red[t], red[t + s]);
        __syncthreads();
    }
    if (t == 0) s_m = red[0];
    __syncthreads();
    float m = s_m;
    if (t < NN) { float e = expf(sdots[t] - m); sdots[t] = e; red[t] = e; }
    __syncthreads();
    for (int s = 64; s > 0; s >>= 1) {
        if (t < s) red[t] += red[t + s];
        __syncthreads();
    }
    if (t == 0) s_sum = red[0];
    __syncthreads();
    float inv = 1.0f / s_sum;

    // weighted sum: half h covers 64 rows of column c (L2-hot from dots pass)
    int c = t & 255, h = t >> 8;
    float4 acc = make_float4(0.f, 0.f, 0.f, 0.f);
    const float4* x4 = (const float4*)xw;
    #pragma unroll 8
    for (int j = h * 64; j < h * 64 + 64; j++) {
        float a = sdots[j] * inv;
        float4 v = x4[j * 256 + c];
        acc.x += a*v.x; acc.y += a*v.y; acc.z += a*v.z; acc.w += a*v.w;
    }
    if (h == 1) sh[c] = acc;
    __syncthreads();
    if (h == 0) {
        float4 b = sh[c];
        acc.x += b.x; acc.y += b.y; acc.z += b.z; acc.w += b.w;
        ((float4*)(g_Y + (size_t)bw * DD))[c] = acc;
    }
}

// ---------------------------------------------------------------------------
// Kernel 5: sum the 16 O partial slabs, bos-shifted broadcast into out[...,1024:]
// ---------------------------------------------------------------------------
__global__ void __launch_bounds__(256) k5_bcast(
    const float* __restrict__ bos, float* __restrict__ out)
{
    int bw = blockIdx.x;
    int w  = bw & (WW - 1);
    int t  = threadIdx.x;
    float val;
    if (w == 0) {
        val = bos[t];
    } else {
        const float* p = g_P2 + (size_t)(bw - 1) * VV + t;
        val = 0.f;
        #pragma unroll
        for (int z = 0; z < 16; z++) val += p[(size_t)z * NBW * VV];
    }
    float* base = out + (size_t)bw * NN * OUTD + DD + t;
    #pragma unroll 4
    for (int j = 0; j < NN; j++) __stcs(&base[(size_t)j * OUTD], val);
}

// ---------------------------------------------------------------------------
extern "C" void kernel_launch(void* const* d_in, const int* in_sizes, int n_in,
                              void* d_out, int out_size) {
    const float* x    = (const float*)d_in[0];
    const int*   mask = (const int*)  d_in[1];
    const float* W_in = (const float*)d_in[2];
    const float* W_q  = (const float*)d_in[3];
    const float* W_k  = (const float*)d_in[4];
    const float* W_v  = (const float*)d_in[5];
    const float* psc  = (const float*)d_in[6];
    const float* bos  = (const float*)d_in[7];
    float* out = (float*)d_out;

    float *pS4, *pLEN, *pWE, *pQ, *pKB, *pY, *pP1, *pP2;
    cudaGetSymbolAddress((void**)&pS4,  g_S4);
    cudaGetSymbolAddress((void**)&pLEN, g_LEN);
    cudaGetSymbolAddress((void**)&pWE,  g_WE);
    cudaGetSymbolAddress((void**)&pQ,   g_Q);
    cudaGetSymbolAddress((void**)&pKB,  g_KB);
    cudaGetSymbolAddress((void**)&pY,   g_Y);
    cudaGetSymbolAddress((void**)&pP1,  g_P1);
    cudaGetSymbolAddress((void**)&pP2,  g_P2);

    prep_kernel<<<PREP_BLOCKS + 2, 256>>>(W_k, mask);
    k1_sum_copy<<<4 * NBW, 256>>>(x, mask, out);

    // F1: (sum4 S4) @ W_in   [512,512] K=1024, split 8 -> 1024 blocks -> P1
    gemm_sk<false, 4><<<dim3(8, 16, 8), 128>>>(pS4, W_in, pP1, PP, DD, PP, 128);
    // R1: WE = relu(sum8 / len)
    reduce_k<1, 8><<<(NBW*PP/4 + 255)/256, 256>>>(pP1, pWE, NBW*PP, PP, pLEN);

    // F2: WE @ W_q   [512,512] K=512, split 8 -> 1024 blocks -> P2
    gemm_sk<false, 1><<<dim3(8, 16, 8), 128>>>(pWE, W_q, pP2, PP, PP, PP, 64);
    // R2: Q = sum8
    reduce_k<0, 8><<<(NBW*PP/4 + 255)/256, 256>>>(pP2, pQ, NBW*PP, PP, nullptr);

    // F3: Q @ KB^T   [512,1152] K=512, split 4 -> 1152 blocks -> P1 (k3 sums)
    gemm_sk<true, 1><<<dim3(18, 16, 4), 128>>>(pQ, pKB, pP1, NKB, PP, PP, 128);

    k3_attn<<<NBW, 512>>>(x, mask, psc);

    // F4: Y @ W_v    [512,256] K=1024, split 16 -> 1024 blocks -> P2 (k5 sums)
    gemm_sk<false, 1><<<dim3(4, 16, 16), 128>>>(pY, W_v, pP2, VV, DD, VV, 64);

    k5_bcast<<<NBW, 256>>>(bos, out);
}

// round 15
// speedup vs baseline: 1.0375x; 1.0375x over previous
#include <cuda_runtime.h>
#include <cuda_bf16.h>
#include <cfloat>
#include <cstddef>

// Problem constants
#define BB 8
#define WW 64
#define NN 128
#define DD 1024
#define PP 512
#define VV 256
#define NBW (BB*WW)          // 512 windows
#define OUTD (DD+VV)         // 1280
#define NKB (DD+NN)          // 1152 combined W_k rows + pos rows
#define PREP_BLOCKS ((NKB*PP+255)/256)   // 2304

// Scratch (device globals; no allocation allowed)
__device__ float g_S  [NBW*DD];      // masked sums per window
__device__ float g_LEN[NBW];         // valid lengths
__device__ float g_WE [NBW*PP];      // reduced WE
__device__ float g_Q  [NBW*PP];      // reduced Q
__device__ float g_KB [NKB*PP];      // [W_k(1024 rows); POS(128 rows)]
__device__ float g_Y  [NBW*DD];      // attn-weighted x sum
__device__ float g_P1 [4*NBW*NKB];   // partials: F1(8x512x512) / F3(4x512x1152)
__device__ float g_P2 [16*NBW*VV];   // partials: F2(8x512x512) / F4(16x512x256)

// ---------------------------------------------------------------------------
// Kernel 1 (fused): blocks [0,512): per-window masked sum over x (sum-only —
// the copy now rides k3's dots pass). Blocks [512, 512+2304): fill g_KB
// (W_k rows + sinusoidal pos rows). Blocks [512+2304, +2): lengths from mask.
// ---------------------------------------------------------------------------
__global__ void __launch_bounds__(256) k1_fused(
    const float* __restrict__ x, const int* __restrict__ mask,
    const float* __restrict__ Wk)
{
    if (blockIdx.x >= NBW) {
        int pb = blockIdx.x - NBW;
        if (pb < PREP_BLOCKS) {
            int idx = pb * 256 + threadIdx.x;
            if (idx >= NKB * PP) return;
            int row = idx >> 9;      // 0..1151
            int i   = idx & 511;
            if (row < DD) {
                g_KB[idx] = Wk[idx];
            } else {
                int j = row - DD;    // pos row 0..127
                const float LOG1E4 = 9.210340371976184f;
                float val;
                if (i < 256) {
                    float invf = expf(-((float)i / 256.0f) * LOG1E4);
                    val = sinf((float)j * invf);
                } else {
                    float invf = expf(-((float)(i - 256) / 256.0f) * LOG1E4);
                    val = cosf((float)j * invf);
                }
                g_KB[idx] = val;
            }
        } else {
            // lengths: one thread per window
            int w = (pb - PREP_BLOCKS) * 256 + threadIdx.x;
            if (w < NBW) {
                const int4* m4 = (const int4*)(mask + (size_t)w * NN);
                int c = 0;
                #pragma unroll 8
                for (int i = 0; i < 32; i++) {
                    int4 v = m4[i];
                    c += (v.x == 0) + (v.y == 0) + (v.z == 0) + (v.w == 0);
                }
                g_LEN[w] = fmaxf((float)c, 1.0f);
            }
        }
        return;
    }

    // ---------- per-window masked sum ----------
    int bw = blockIdx.x;
    int t  = threadIdx.x;
    __shared__ int smask[NN];
    if (t < NN) smask[t] = mask[bw * NN + t];
    __syncthreads();

    const float4* x4 = (const float4*)(x + (size_t)bw * NN * DD);
    float4 acc0 = make_float4(0.f, 0.f, 0.f, 0.f);
    float4 acc1 = make_float4(0.f, 0.f, 0.f, 0.f);
    #pragma unroll 4
    for (int j = 0; j < 64; j++) {
        float4 v0 = x4[j * 256 + t];
        float4 v1 = x4[(j + 64) * 256 + t];
        if (smask[j] == 0) {
            acc0.x += v0.x; acc0.y += v0.y; acc0.z += v0.z; acc0.w += v0.w;
        }
        if (smask[j + 64] == 0) {
            acc1.x += v1.x; acc1.y += v1.y; acc1.z += v1.z; acc1.w += v1.w;
        }
    }
    acc0.x += acc1.x; acc0.y += acc1.y; acc0.z += acc1.z; acc0.w += acc1.w;
    ((float4*)g_S)[bw * 256 + t] = acc0;
}

// ---------------------------------------------------------------------------
// Split-K GEMM (proven 32x64 config). grid = (N/64, 16, SPLIT). 128 thr,
// 4x4 microtile, BK=16, double-buffered smem, register prefetch, one sync
// per stage. TB=0: B is [K,N] (ldb=N); TB=1: B is [N,K] (ldb=K).
// Output: partial slab part[bz][512][N].
// ---------------------------------------------------------------------------
template<bool TB>
__global__ void __launch_bounds__(128) gemm_sk(
    const float* __restrict__ A, const float* __restrict__ B,
    float* __restrict__ part, int N, int lda, int ldb, int Kchunk)
{
    __shared__ float As[2][16][33];
    __shared__ float Bs[2][16][68];
    const int tid = threadIdx.x;
    const int row0  = blockIdx.y * 32;
    const int col0  = blockIdx.x * 64;
    const int kbase = blockIdx.z * Kchunk;

    const int ty = tid >> 4, tx = tid & 15;
    const int arow = tid >> 2;
    const int akc  = (tid & 3) << 2;
    const float* Ag = A + (size_t)(row0 + arow) * lda + kbase + akc;

    const int bk  = tid >> 3;
    const int bn  = (tid & 7) << 3;
    const int tn  = tid & 63;
    const int tkh = (tid >> 6) << 3;

    float acc[4][4] = {};
    float4 ra, rb0, rb1;

    ra = *(const float4*)Ag;
    if (!TB) {
        const float* bp = B + (size_t)(kbase + bk) * ldb + col0 + bn;
        rb0 = *(const float4*)bp; rb1 = *(const float4*)(bp + 4);
    } else {
        const float* bp = B + (size_t)(col0 + tn) * ldb + kbase + tkh;
        rb0 = *(const float4*)bp; rb1 = *(const float4*)(bp + 4);
    }
    As[0][akc+0][arow] = ra.x; As[0][akc+1][arow] = ra.y;
    As[0][akc+2][arow] = ra.z; As[0][akc+3][arow] = ra.w;
    if (!TB) {
        *(float4*)&Bs[0][bk][bn]     = rb0;
        *(float4*)&Bs[0][bk][bn + 4] = rb1;
    } else {
        Bs[0][tkh+0][tn] = rb0.x; Bs[0][tkh+1][tn] = rb0.y;
        Bs[0][tkh+2][tn] = rb0.z; Bs[0][tkh+3][tn] = rb0.w;
        Bs[0][tkh+4][tn] = rb1.x; Bs[0][tkh+5][tn] = rb1.y;
        Bs[0][tkh+6][tn] = rb1.z; Bs[0][tkh+7][tn] = rb1.w;
    }
    __syncthreads();

    const int nst = Kchunk >> 4;
    for (int s = 0; s < nst; s++) {
        const int cur = s & 1;
        if (s + 1 < nst) {
            const int k0 = (s + 1) << 4;
            ra = *(const float4*)(Ag + k0);
            if (!TB) {
                const float* bp = B + (size_t)(kbase + k0 + bk) * ldb + col0 + bn;
                rb0 = *(const float4*)bp; rb1 = *(const float4*)(bp + 4);
            } else {
                const float* bp = B + (size_t)(col0 + tn) * ldb + kbase + k0 + tkh;
                rb0 = *(const float4*)bp; rb1 = *(const float4*)(bp + 4);
            }
        }
        #pragma unroll
        for (int kk = 0; kk < 16; kk++) {
            float a[4], b[4];
            #pragma unroll
            for (int i = 0; i < 4; i++) a[i] = As[cur][kk][ty + 8 * i];
            #pragma unroll
            for (int j = 0; j < 4; j++) b[j] = Bs[cur][kk][tx + 16 * j];
            #pragma unroll
            for (int i = 0; i < 4; i++)
                #pragma unroll
                for (int j = 0; j < 4; j++)
                    acc[i][j] = fmaf(a[i], b[j], acc[i][j]);
        }
        if (s + 1 < nst) {
            const int nxt = cur ^ 1;
            As[nxt][akc+0][arow] = ra.x; As[nxt][akc+1][arow] = ra.y;
            As[nxt][akc+2][arow] = ra.z; As[nxt][akc+3][arow] = ra.w;
            if (!TB) {
                *(float4*)&Bs[nxt][bk][bn]     = rb0;
                *(float4*)&Bs[nxt][bk][bn + 4] = rb1;
            } else {
                Bs[nxt][tkh+0][tn] = rb0.x; Bs[nxt][tkh+1][tn] = rb0.y;
                Bs[nxt][tkh+2][tn] = rb0.z; Bs[nxt][tkh+3][tn] = rb0.w;
                Bs[nxt][tkh+4][tn] = rb1.x; Bs[nxt][tkh+5][tn] = rb1.y;
                Bs[nxt][tkh+6][tn] = rb1.z; Bs[nxt][tkh+7][tn] = rb1.w;
            }
            __syncthreads();
        }
    }

    float* Cp = part + (size_t)blockIdx.z * NBW * N;
    #pragma unroll
    for (int i = 0; i < 4; i++) {
        const int m = row0 + ty + 8 * i;
        #pragma unroll
        for (int j = 0; j < 4; j++)
            Cp[(size_t)m * N + col0 + tx + 16 * j] = acc[i][j];
    }
}

// ---------------------------------------------------------------------------
// reduce_k: C = sum of SPLIT partial slabs; EPI==1: relu(sum / lenv[row]).
// ---------------------------------------------------------------------------
template<int EPI, int SPLIT>
__global__ void __launch_bounds__(256) reduce_k(
    const float* __restrict__ part, float* __restrict__ C,
    int MN, int N, const float* __restrict__ lenv)
{
    int idx4 = blockIdx.x * blockDim.x + threadIdx.x;
    if (idx4 * 4 >= MN) return;
    const float4* p4 = (const float4*)part;
    float4 s = p4[idx4];
    #pragma unroll
    for (int z = 1; z < SPLIT; z++) {
        float4 v = p4[(size_t)z * (MN / 4) + idx4];
        s.x += v.x; s.y += v.y; s.z += v.z; s.w += v.w;
    }
    if (EPI == 1) {
        int row = (idx4 * 4) / N;
        float inv = 1.0f / lenv[row];
        s.x = fmaxf(s.x * inv, 0.f); s.y = fmaxf(s.y * inv, 0.f);
        s.z = fmaxf(s.z * inv, 0.f); s.w = fmaxf(s.w * inv, 0.f);
    }
    ((float4*)C)[idx4] = s;
}

// ---------------------------------------------------------------------------
// Kernel 3: per-window attention + FUSED x->out[..., :1024] copy.
// The dots pass touches every element of x exactly once, so it also streams
// the copy out with __stcs (same addresses, fully coalesced).
// Sums the 4 RPB partial slabs on load. 256 threads.
// ---------------------------------------------------------------------------
__global__ void __launch_bounds__(256) k3_attn(
    const float* __restrict__ x, const int* __restrict__ mask,
    const float* __restrict__ ps_ptr, float* __restrict__ out)
{
    int bw = blockIdx.x;
    int t = threadIdx.x;
    int warp = t >> 5, lane = t & 31;
    __shared__ float sr[DD];
    __shared__ float spb[NN];
    __shared__ float sdots[NN];
    __shared__ float red[NN];
    __shared__ float s_m, s_sum;

    const float* rp = g_P1 + (size_t)bw * NKB;
    const size_t SL = (size_t)NBW * NKB;
    {
        float4 a = ((const float4*)rp)[t];
        #pragma unroll
        for (int z = 1; z < 4; z++) {
            float4 b = ((const float4*)(rp + z * SL))[t];
            a.x += b.x; a.y += b.y; a.z += b.z; a.w += b.w;
        }
        ((float4*)sr)[t] = a;
    }
    if (t < NN) {
        float v = rp[DD + t];
        #pragma unroll
        for (int z = 1; z < 4; z++) v += rp[z * SL + DD + t];
        spb[t] = v;
    }
    __syncthreads();

    const float* xw = x + (size_t)bw * NN * DD;
    float* ow = out + (size_t)bw * NN * OUTD;
    float ps = ps_ptr[0];
    const float rs = 0.044194173824159216f;   // 512^-0.5

    // dots + copy: each warp handles row pairs (j, j+64)
    for (int j = warp; j < 64; j += 8) {
        const float4* row0 = (const float4*)(xw + (size_t)j * DD);
        const float4* row1 = (const float4*)(xw + (size_t)(j + 64) * DD);
        float4* or0 = (float4*)(ow + (size_t)j * OUTD);
        float4* or1 = (float4*)(ow + (size_t)(j + 64) * OUTD);
        const float4* r4 = (const float4*)sr;
        float s0 = 0.f, s1 = 0.f;
        #pragma unroll
        for (int it = 0; it < 8; it++) {
            float4 v0 = row0[lane + it * 32];
            float4 v1 = row1[lane + it * 32];
            __stcs(&or0[lane + it * 32], v0);
            __stcs(&or1[lane + it * 32], v1);
            float4 r = r4[lane + it * 32];
            s0 += v0.x*r.x + v0.y*r.y + v0.z*r.z + v0.w*r.w;
            s1 += v1.x*r.x + v1.y*r.y + v1.z*r.z + v1.w*r.w;
        }
        #pragma unroll
        for (int o = 16; o > 0; o >>= 1) {
            s0 += __shfl_xor_sync(0xffffffffu, s0, o);
            s1 += __shfl_xor_sync(0xffffffffu, s1, o);
        }
        if (lane == 0) {
            sdots[j]      = (mask[bw * NN + j]      != 0) ? -FLT_MAX : (s0 + ps * spb[j])      * rs;
            sdots[j + 64] = (mask[bw * NN + j + 64] != 0) ? -FLT_MAX : (s1 + ps * spb[j + 64]) * rs;
        }
    }
    __syncthreads();

    // softmax over 128 values
    if (t < NN) red[t] = sdots[t];
    __syncthreads();
    for (int s = 64; s > 0; s >>= 1) {
        if (t < s) red[t] = fmaxf(red[t], red[t + s]);
        __syncthreads();
    }
    if (t == 0) s_m = red[0];
    __syncthreads();
    float m = s_m;
    if (t < NN) { float e = expf(sdots[t] - m); sdots[t] = e; red[t] = e; }
    __syncthreads();
    for (int s = 64; s > 0; s >>= 1) {
        if (t < s) red[t] += red[t + s];
        __syncthreads();
    }
    if (t == 0) s_sum = red[0];
    __syncthreads();
    float inv = 1.0f / s_sum;

    // weighted sum over rows (window is L2-hot from the dots pass)
    float4 acc = make_float4(0.f, 0.f, 0.f, 0.f);
    const float4* x4 = (const float4*)xw;
    #pragma unroll 8
    for (int j = 0; j < NN; j++) {
        float a = sdots[j] * inv;
        float4 v = x4[j * 256 + t];
        acc.x += a*v.x; acc.y += a*v.y; acc.z += a*v.z; acc.w += a*v.w;
    }
    ((float4*)(g_Y + (size_t)bw * DD))[t] = acc;
}

// ---------------------------------------------------------------------------
// Kernel 5: sum the 16 O partial slabs, bos-shifted broadcast into out[...,1024:]
// ---------------------------------------------------------------------------
__global__ void __launch_bounds__(256) k5_bcast(
    const float* __restrict__ bos, float* __restrict__ out)
{
    int bw = blockIdx.x;
    int w  = bw & (WW - 1);
    int t  = threadIdx.x;
    float val;
    if (w == 0) {
        val = bos[t];
    } else {
        const float* p = g_P2 + (size_t)(bw - 1) * VV + t;
        val = 0.f;
        #pragma unroll
        for (int z = 0; z < 16; z++) val += p[(size_t)z * NBW * VV];
    }
    float* base = out + (size_t)bw * NN * OUTD + DD + t;
    #pragma unroll 4
    for (int j = 0; j < NN; j++) __stcs(&base[(size_t)j * OUTD], val);
}

// ---------------------------------------------------------------------------
extern "C" void kernel_launch(void* const* d_in, const int* in_sizes, int n_in,
                              void* d_out, int out_size) {
    const float* x    = (const float*)d_in[0];
    const int*   mask = (const int*)  d_in[1];
    const float* W_in = (const float*)d_in[2];
    const float* W_q  = (const float*)d_in[3];
    const float* W_k  = (const float*)d_in[4];
    const float* W_v  = (const float*)d_in[5];
    const float* psc  = (const float*)d_in[6];
    const float* bos  = (const float*)d_in[7];
    float* out = (float*)d_out;

    float *pS, *pLEN, *pWE, *pQ, *pKB, *pY, *pP1, *pP2;
    cudaGetSymbolAddress((void**)&pS,   g_S);
    cudaGetSymbolAddress((void**)&pLEN, g_LEN);
    cudaGetSymbolAddress((void**)&pWE,  g_WE);
    cudaGetSymbolAddress((void**)&pQ,   g_Q);
    cudaGetSymbolAddress((void**)&pKB,  g_KB);
    cudaGetSymbolAddress((void**)&pY,   g_Y);
    cudaGetSymbolAddress((void**)&pP1,  g_P1);
    cudaGetSymbolAddress((void**)&pP2,  g_P2);

    // k1: per-window sums (512 blocks) + prep (2304 KB blocks + 2 length blocks)
    k1_fused<<<NBW + PREP_BLOCKS + 2, 256>>>(x, mask, W_k);

    // F1: S @ W_in     [512,512] K=1024, split 8 -> 1024 blocks -> P1
    gemm_sk<false><<<dim3(8, 16, 8), 128>>>(pS,  W_in, pP1, PP,  DD, PP, 128);
    // R1: WE = relu(sum8 / len)
    reduce_k<1, 8><<<(NBW*PP/4 + 255)/256, 256>>>(pP1, pWE, NBW*PP, PP, pLEN);

    // F2: WE @ W_q     [512,512] K=512, split 8 -> 1024 blocks -> P2
    gemm_sk<false><<<dim3(8, 16, 8), 128>>>(pWE, W_q,  pP2, PP,  PP, PP, 64);
    // R2: Q = sum8
    reduce_k<0, 8><<<(NBW*PP/4 + 255)/256, 256>>>(pP2, pQ, NBW*PP, PP, nullptr);

    // F3: Q @ KB^T     [512,1152] K=512, split 4 -> 1152 blocks -> P1 (k3 sums)
    gemm_sk<true><<<dim3(18, 16, 4), 128>>>(pQ, pKB, pP1, NKB, PP, PP, 128);

    // k3: attention + fused copy of x into out[..., :1024]
    k3_attn<<<NBW, 256>>>(x, mask, psc, out);

    // F4: Y @ W_v      [512,256] K=1024, split 16 -> 1024 blocks -> P2 (k5 sums)
    gemm_sk<false><<<dim3(4, 16, 16), 128>>>(pY, W_v, pP2, VV, DD, VV, 64);

    k5_bcast<<<NBW, 256>>>(bos, out);
}